// round 1
// baseline (speedup 1.0000x reference)
#include <cuda_runtime.h>
#include <stdint.h>

// Problem geometry (fixed for this instance: act = (4, 4096, 4096) fp32)
#define DCOL 4096        // last-dim size
#define GRP  32          // group size
#define NG   (DCOL/GRP)  // 128 groups (scales reduce over batch+rows+group)
#define F4_PER_ROW (DCOL/4)  // 1024 float4 per row

// Scratch (no device allocation allowed -> __device__ globals)
__device__ unsigned int g_maxbits[NG];
__device__ float        g_inv_s8[NG];  // 8 / scale  (exact power of 2)
__device__ float        g_s8[NG];      // scale / 8  (exact power of 2)

// ---------------------------------------------------------------------------
// Kernel 0: reset the atomic-max scratch so every graph replay is identical.
// ---------------------------------------------------------------------------
__global__ void k_zero()
{
    if (threadIdx.x < NG) g_maxbits[threadIdx.x] = 0u;
}

// ---------------------------------------------------------------------------
// Kernel 1: per-group max|x| over ALL rows.
// Thread j (0..1023) owns float4-column j => fixed group g = j>>3.
// Grid-stride over rows, register max, 8-lane shfl reduce, 1 atomicMax/group.
// Non-negative floats: uint bit pattern is order-preserving -> atomicMax(uint).
// ---------------------------------------------------------------------------
__global__ __launch_bounds__(1024, 2)
void k_pass1(const float4* __restrict__ act, int rows)
{
    const int j = threadIdx.x;
    float m = 0.0f;

    int r = blockIdx.x;
    const int stride = gridDim.x;
    // unroll x4 for memory-level parallelism
    for (; r + 3 * stride < rows; r += 4 * stride) {
        float4 v0 = act[(size_t)(r + 0 * stride) * F4_PER_ROW + j];
        float4 v1 = act[(size_t)(r + 1 * stride) * F4_PER_ROW + j];
        float4 v2 = act[(size_t)(r + 2 * stride) * F4_PER_ROW + j];
        float4 v3 = act[(size_t)(r + 3 * stride) * F4_PER_ROW + j];
        float m0 = fmaxf(fmaxf(fabsf(v0.x), fabsf(v0.y)), fmaxf(fabsf(v0.z), fabsf(v0.w)));
        float m1 = fmaxf(fmaxf(fabsf(v1.x), fabsf(v1.y)), fmaxf(fabsf(v1.z), fabsf(v1.w)));
        float m2 = fmaxf(fmaxf(fabsf(v2.x), fabsf(v2.y)), fmaxf(fabsf(v2.z), fabsf(v2.w)));
        float m3 = fmaxf(fmaxf(fabsf(v3.x), fabsf(v3.y)), fmaxf(fabsf(v3.z), fabsf(v3.w)));
        m = fmaxf(m, fmaxf(fmaxf(m0, m1), fmaxf(m2, m3)));
    }
    for (; r < rows; r += stride) {
        float4 v = act[(size_t)r * F4_PER_ROW + j];
        m = fmaxf(m, fmaxf(fmaxf(fabsf(v.x), fabsf(v.y)), fmaxf(fabsf(v.z), fabsf(v.w))));
    }

    // Reduce across the 8 lanes that share a group (j>>3 constant within xor 4,2,1)
    m = fmaxf(m, __shfl_xor_sync(0xffffffffu, m, 4));
    m = fmaxf(m, __shfl_xor_sync(0xffffffffu, m, 2));
    m = fmaxf(m, __shfl_xor_sync(0xffffffffu, m, 1));

    if ((j & 7) == 0)
        atomicMax(&g_maxbits[j >> 3], __float_as_uint(m));
}

// ---------------------------------------------------------------------------
// Kernel 2: exps = floor(log2(max)) via exact exponent-field extraction;
// write exps to output tail; precompute 8/s and s/8 (exact powers of 2).
// ---------------------------------------------------------------------------
__global__ void k_finalize(float* __restrict__ exps_out)
{
    const int g = threadIdx.x;
    if (g >= NG) return;
    const float ma = __uint_as_float(g_maxbits[g]);
    int e;
    float s;
    if (ma > 0.0f) {
        e = (int)((__float_as_uint(ma) >> 23) & 0xFFu) - 127;  // exact floor(log2)
        s = __uint_as_float((unsigned)(e + 127) << 23);        // 2^e
    } else {
        e = 0; s = 1.0f;
    }
    exps_out[g]  = (float)e;
    g_inv_s8[g]  = 8.0f / s;   // exact
    g_s8[g]      = s * 0.125f; // exact
}

// ---------------------------------------------------------------------------
// Kernel 3: quantize.  q = copysign( rint( min(|a|*8/s, 8) ) * s/8, a )
// Same column-fixed mapping; scales loaded once per thread.
// Rows iterated in REVERSE so pass1's most-recently-touched rows may still
// be resident in L2 (126 MB) -> fewer HBM reads.
// ---------------------------------------------------------------------------
__global__ __launch_bounds__(1024, 2)
void k_pass2(const float4* __restrict__ act, float4* __restrict__ q, int rows)
{
    const int j = threadIdx.x;
    const int g = j >> 3;
    const float inv_s8 = g_inv_s8[g];
    const float s8     = g_s8[g];

    for (int rb = blockIdx.x; rb < rows; rb += gridDim.x) {
        const int r = rows - 1 - rb;
        const size_t idx = (size_t)r * F4_PER_ROW + j;
        float4 v = act[idx];
        float4 o;
        o.x = copysignf(rintf(fminf(fabsf(v.x) * inv_s8, 8.0f)) * s8, v.x);
        o.y = copysignf(rintf(fminf(fabsf(v.y) * inv_s8, 8.0f)) * s8, v.y);
        o.z = copysignf(rintf(fminf(fabsf(v.z) * inv_s8, 8.0f)) * s8, v.z);
        o.w = copysignf(rintf(fminf(fabsf(v.w) * inv_s8, 8.0f)) * s8, v.w);
        q[idx] = o;
    }
}

// ---------------------------------------------------------------------------
extern "C" void kernel_launch(void* const* d_in, const int* in_sizes, int n_in,
                              void* d_out, int out_size)
{
    const float4* act = (const float4*)d_in[0];
    float*        out = (float*)d_out;
    const int total = in_sizes[0];       // 4*4096*4096 = 67108864
    const int rows  = total / DCOL;      // 16384

    k_zero<<<1, 128>>>();
    k_pass1<<<512, 1024>>>(act, rows);
    k_finalize<<<1, 128>>>(out + (size_t)total);   // exps appended after q
    k_pass2<<<1024, 1024>>>(act, (float4*)d_out, rows);
}

// round 3
// speedup vs baseline: 1.0010x; 1.0010x over previous
#include <cuda_runtime.h>
#include <stdint.h>

// Problem geometry (fixed for this instance: act = (4, 4096, 4096) fp32)
#define DCOL 4096        // last-dim size
#define GRP  32          // group size
#define NG   (DCOL/GRP)  // 128 groups (scales reduce over batch+rows+group)
#define F4_PER_ROW (DCOL/4)  // 1024 float4 per row

// Scratch (no device allocation allowed -> __device__ globals)
__device__ unsigned int g_maxbits[NG];
__device__ float        g_inv_s8[NG];  // 8 / scale  (exact power of 2)
__device__ float        g_s8[NG];      // scale / 8  (exact power of 2)

// ---------------------------------------------------------------------------
// Kernel 0: reset the atomic-max scratch so every graph replay is identical.
// ---------------------------------------------------------------------------
__global__ void k_zero()
{
    if (threadIdx.x < NG) g_maxbits[threadIdx.x] = 0u;
}

// ---------------------------------------------------------------------------
// Kernel 1: per-group max|x| over ALL rows.
// Thread j (0..1023) owns float4-column j => fixed group g = j>>3.
// Grid-stride over rows, register max, 8-lane shfl reduce, 1 atomicMax/group.
// Non-negative floats: uint bit pattern is order-preserving -> atomicMax(uint).
// ---------------------------------------------------------------------------
__global__ __launch_bounds__(1024, 2)
void k_pass1(const float4* __restrict__ act, int rows)
{
    const int j = threadIdx.x;
    float m = 0.0f;

    int r = blockIdx.x;
    const int stride = gridDim.x;
    // unroll x4 for memory-level parallelism
    for (; r + 3 * stride < rows; r += 4 * stride) {
        float4 v0 = act[(size_t)(r + 0 * stride) * F4_PER_ROW + j];
        float4 v1 = act[(size_t)(r + 1 * stride) * F4_PER_ROW + j];
        float4 v2 = act[(size_t)(r + 2 * stride) * F4_PER_ROW + j];
        float4 v3 = act[(size_t)(r + 3 * stride) * F4_PER_ROW + j];
        float m0 = fmaxf(fmaxf(fabsf(v0.x), fabsf(v0.y)), fmaxf(fabsf(v0.z), fabsf(v0.w)));
        float m1 = fmaxf(fmaxf(fabsf(v1.x), fabsf(v1.y)), fmaxf(fabsf(v1.z), fabsf(v1.w)));
        float m2 = fmaxf(fmaxf(fabsf(v2.x), fabsf(v2.y)), fmaxf(fabsf(v2.z), fabsf(v2.w)));
        float m3 = fmaxf(fmaxf(fabsf(v3.x), fabsf(v3.y)), fmaxf(fabsf(v3.z), fabsf(v3.w)));
        m = fmaxf(m, fmaxf(fmaxf(m0, m1), fmaxf(m2, m3)));
    }
    for (; r < rows; r += stride) {
        float4 v = act[(size_t)r * F4_PER_ROW + j];
        m = fmaxf(m, fmaxf(fmaxf(fabsf(v.x), fabsf(v.y)), fmaxf(fabsf(v.z), fabsf(v.w))));
    }

    // Reduce across the 8 lanes that share a group (j>>3 constant within xor 4,2,1)
    m = fmaxf(m, __shfl_xor_sync(0xffffffffu, m, 4));
    m = fmaxf(m, __shfl_xor_sync(0xffffffffu, m, 2));
    m = fmaxf(m, __shfl_xor_sync(0xffffffffu, m, 1));

    if ((j & 7) == 0)
        atomicMax(&g_maxbits[j >> 3], __float_as_uint(m));
}

// ---------------------------------------------------------------------------
// Kernel 2: exps = floor(log2(max)) via exact exponent-field extraction;
// write exps to output tail; precompute 8/s and s/8 (exact powers of 2).
// ---------------------------------------------------------------------------
__global__ void k_finalize(float* __restrict__ exps_out)
{
    const int g = threadIdx.x;
    if (g >= NG) return;
    const float ma = __uint_as_float(g_maxbits[g]);
    int e;
    float s;
    if (ma > 0.0f) {
        e = (int)((__float_as_uint(ma) >> 23) & 0xFFu) - 127;  // exact floor(log2)
        s = __uint_as_float((unsigned)(e + 127) << 23);        // 2^e
    } else {
        e = 0; s = 1.0f;
    }
    exps_out[g]  = (float)e;
    g_inv_s8[g]  = 8.0f / s;   // exact
    g_s8[g]      = s * 0.125f; // exact
}

// ---------------------------------------------------------------------------
// Kernel 3: quantize.  q = copysign( rint( min(|a|*8/s, 8) ) * s/8, a )
// Same column-fixed mapping; scales loaded once per thread.
// Rows iterated in REVERSE so pass1's most-recently-touched rows may still
// be resident in L2 (126 MB) -> fewer HBM reads.
// ---------------------------------------------------------------------------
__global__ __launch_bounds__(1024, 2)
void k_pass2(const float4* __restrict__ act, float4* __restrict__ q, int rows)
{
    const int j = threadIdx.x;
    const int g = j >> 3;
    const float inv_s8 = g_inv_s8[g];
    const float s8     = g_s8[g];

    for (int rb = blockIdx.x; rb < rows; rb += gridDim.x) {
        const int r = rows - 1 - rb;
        const size_t idx = (size_t)r * F4_PER_ROW + j;
        float4 v = act[idx];
        float4 o;
        o.x = copysignf(rintf(fminf(fabsf(v.x) * inv_s8, 8.0f)) * s8, v.x);
        o.y = copysignf(rintf(fminf(fabsf(v.y) * inv_s8, 8.0f)) * s8, v.y);
        o.z = copysignf(rintf(fminf(fabsf(v.z) * inv_s8, 8.0f)) * s8, v.z);
        o.w = copysignf(rintf(fminf(fabsf(v.w) * inv_s8, 8.0f)) * s8, v.w);
        q[idx] = o;
    }
}

// ---------------------------------------------------------------------------
extern "C" void kernel_launch(void* const* d_in, const int* in_sizes, int n_in,
                              void* d_out, int out_size)
{
    const float4* act = (const float4*)d_in[0];
    float*        out = (float*)d_out;
    const int total = in_sizes[0];       // 4*4096*4096 = 67108864
    const int rows  = total / DCOL;      // 16384

    k_zero<<<1, 128>>>();
    k_pass1<<<512, 1024>>>(act, rows);
    k_finalize<<<1, 128>>>(out + (size_t)total);   // exps appended after q
    k_pass2<<<1024, 1024>>>(act, (float4*)d_out, rows);
}

// round 4
// speedup vs baseline: 1.0139x; 1.0129x over previous
#include <cuda_runtime.h>
#include <stdint.h>

// Problem geometry (fixed: act = (4, 4096, 4096) fp32)
#define DCOL 4096
#define GRP  32
#define NG   (DCOL/GRP)      // 128 groups (reduced over batch+rows+group)
#define F4_PER_ROW (DCOL/4)  // 1024 float4 per row

// Scratch (__device__ globals; no allocation allowed)
__device__ unsigned int g_maxbits[NG];
__device__ unsigned int g_arrive;

// ---------------------------------------------------------------------------
// Kernel 0: reset scratch so every graph replay is identical.
// ---------------------------------------------------------------------------
__global__ void k_zero()
{
    if (threadIdx.x < NG) g_maxbits[threadIdx.x] = 0u;
    if (threadIdx.x == 0) g_arrive = 0u;
}

// ---------------------------------------------------------------------------
// Fused persistent kernel.
//   Phase 1: each block max-reduces |x| over ITS OWN contiguous row chunk,
//            one atomicMax per group per block.
//   Barrier: global arrive counter (all blocks are co-resident by construction:
//            grid = numSMs * max-active-blocks from the occupancy API).
//   Phase 2: same block re-reads its own chunk in REVERSE row order (LIFO vs
//            L2 recency -> the chunk tail is still L2-resident), quantizes,
//            and stores with .cs (evict-first) so writes don't evict act.
// Thread j (0..1023) owns float4-column j => fixed group g = j>>3.
// ---------------------------------------------------------------------------
__global__ __launch_bounds__(1024, 2)
void k_fused(const float4* __restrict__ act, float4* __restrict__ q,
             float* __restrict__ exps_out, int rows)
{
    const int j  = threadIdx.x;
    const int nb = gridDim.x;
    const int b  = blockIdx.x;

    // Contiguous row chunk for this block
    const int per = rows / nb;
    const int rem = rows % nb;
    const int r0  = b * per + (b < rem ? b : rem);
    const int r1  = r0 + per + (b < rem ? 1 : 0);

    // ---------- Phase 1: chunk max ----------
    float m = 0.0f;
    int r = r0;
    for (; r + 3 < r1; r += 4) {
        float4 v0 = act[(size_t)(r + 0) * F4_PER_ROW + j];
        float4 v1 = act[(size_t)(r + 1) * F4_PER_ROW + j];
        float4 v2 = act[(size_t)(r + 2) * F4_PER_ROW + j];
        float4 v3 = act[(size_t)(r + 3) * F4_PER_ROW + j];
        float m0 = fmaxf(fmaxf(fabsf(v0.x), fabsf(v0.y)), fmaxf(fabsf(v0.z), fabsf(v0.w)));
        float m1 = fmaxf(fmaxf(fabsf(v1.x), fabsf(v1.y)), fmaxf(fabsf(v1.z), fabsf(v1.w)));
        float m2 = fmaxf(fmaxf(fabsf(v2.x), fabsf(v2.y)), fmaxf(fabsf(v2.z), fabsf(v2.w)));
        float m3 = fmaxf(fmaxf(fabsf(v3.x), fabsf(v3.y)), fmaxf(fabsf(v3.z), fabsf(v3.w)));
        m = fmaxf(m, fmaxf(fmaxf(m0, m1), fmaxf(m2, m3)));
    }
    for (; r < r1; ++r) {
        float4 v = act[(size_t)r * F4_PER_ROW + j];
        m = fmaxf(m, fmaxf(fmaxf(fabsf(v.x), fabsf(v.y)), fmaxf(fabsf(v.z), fabsf(v.w))));
    }

    // 8-lane reduce within the group (j>>3 constant under xor 4,2,1)
    m = fmaxf(m, __shfl_xor_sync(0xffffffffu, m, 4));
    m = fmaxf(m, __shfl_xor_sync(0xffffffffu, m, 2));
    m = fmaxf(m, __shfl_xor_sync(0xffffffffu, m, 1));
    if ((j & 7) == 0)
        atomicMax(&g_maxbits[j >> 3], __float_as_uint(m));

    // ---------- Device-wide barrier ----------
    __syncthreads();                 // all warps' atomicMax issued
    __threadfence();                 // make them visible device-wide
    if (j == 0) {
        atomicAdd(&g_arrive, 1u);
        while (atomicAdd(&g_arrive, 0u) < (unsigned)nb) { /* spin */ }
    }
    __syncthreads();

    // ---------- Scales (atomics live in L2; bypass L1 with ldcg) ----------
    const int g = j >> 3;
    const float ma = __uint_as_float(__ldcg(&g_maxbits[g]));
    int e; float s;
    if (ma > 0.0f) {
        e = (int)((__float_as_uint(ma) >> 23) & 0xFFu) - 127;  // exact floor(log2)
        s = __uint_as_float((unsigned)(e + 127) << 23);        // 2^e exact
    } else {
        e = 0; s = 1.0f;
    }
    const float inv_s8 = 8.0f / s;     // exact power of 2
    const float s8     = s * 0.125f;   // exact power of 2

    if (b == 0 && j < NG && (j & 7) == (j & 7)) {
        // one writer per group value: threads 0..127 each hold distinct g only
        // for j<128 when g=j>>3 repeats; write from the canonical lane instead:
    }
    if (b == 0 && j < NG) {
        // recompute for THIS index (j in [0,128) is the group id here)
        const float ma2 = __uint_as_float(__ldcg(&g_maxbits[j]));
        float e2 = (ma2 > 0.0f)
                 ? (float)((int)((__float_as_uint(ma2) >> 23) & 0xFFu) - 127)
                 : 0.0f;
        exps_out[j] = e2;
    }

    // ---------- Phase 2: quantize own chunk in reverse (LIFO vs L2) ----------
    for (int rr = r1 - 1; rr >= r0; --rr) {
        const size_t idx = (size_t)rr * F4_PER_ROW + j;
        float4 v = act[idx];
        float4 o;
        o.x = copysignf(rintf(fminf(fabsf(v.x) * inv_s8, 8.0f)) * s8, v.x);
        o.y = copysignf(rintf(fminf(fabsf(v.y) * inv_s8, 8.0f)) * s8, v.y);
        o.z = copysignf(rintf(fminf(fabsf(v.z) * inv_s8, 8.0f)) * s8, v.z);
        o.w = copysignf(rintf(fminf(fabsf(v.w) * inv_s8, 8.0f)) * s8, v.w);
        __stcs(&q[idx], o);          // evict-first: don't pollute L2 with q
    }
}

// ---------------------------------------------------------------------------
extern "C" void kernel_launch(void* const* d_in, const int* in_sizes, int n_in,
                              void* d_out, int out_size)
{
    const float4* act = (const float4*)d_in[0];
    float*        out = (float*)d_out;
    const int total = in_sizes[0];   // 67108864
    const int rows  = total / DCOL;  // 16384

    // Grid sized to guaranteed co-residency (spin barrier safety)
    int dev = 0, numSMs = 148, bpm = 2;
    cudaGetDevice(&dev);
    cudaDeviceGetAttribute(&numSMs, cudaDevAttrMultiProcessorCount, dev);
    cudaOccupancyMaxActiveBlocksPerMultiprocessor(&bpm, k_fused, 1024, 0);
    if (bpm < 1) bpm = 1;
    int grid = numSMs * bpm;
    if (grid > rows) grid = rows;

    k_zero<<<1, 128>>>();
    k_fused<<<grid, 1024>>>(act, (float4*)d_out, out + (size_t)total, rows);
}